// round 13
// baseline (speedup 1.0000x reference)
#include <cuda_runtime.h>

// Gibbs sweep over DIM=32 coordinates of B rows (triangular form).
// x_new = forward_subst(I-L) applied to (base + U x_old);
// A = -P_ij/P_ii (diag 0) split into strict upper U / lower L, both in
// __constant__ as zero-masked float4 columns (LDCU/LDC port, off MIO).
//
// R12: overlap + wide-op staging.
//  * all 16 LDG.128 (noise + x) front-issued into two swizzled float4 buffers
//  * base init and phase-1 x consumption via LDS.128 chunks (4 floats live)
//  * zero scalar smem ops; out-stage reuses the x buffer

#define DIM 32
#define THREADS 128
#define ROWS_PER_BLOCK 128

__device__   float  g_T[2 * DIM * DIM];  // [0..1023] upper-masked, [1024..] lower-masked
__device__   float  g_SM[2 * DIM];       // [0..31] sigma, [32..63] mu
__constant__ float4 c_T4[2 * DIM * 8];   // col j: c_T4[j*8+q] (U), c_T4[256+j*8+q] (L)
__constant__ float2 c_SG2[DIM / 2];
__constant__ float2 c_MU2[DIM / 2];

__global__ void prep_kernel(const float* __restrict__ P,
                            const float* __restrict__ mu)
{
    int e = threadIdx.x;                 // 1024 threads
    int j = e >> 5, k = e & 31;          // column j, row k
    float a = -P[k * DIM + j] / P[k * DIM + k];   // A[k][j]
    g_T[e]              = (k < j) ? a : 0.0f;     // strict upper
    g_T[DIM * DIM + e]  = (k > j) ? a : 0.0f;     // strict lower
    if (e < DIM) {
        g_SM[e]       = sqrtf(1.0f / P[e * DIM + e]);
        g_SM[DIM + e] = mu[e];
    }
}

__device__ __forceinline__ unsigned long long f2u(float2 v) {
    unsigned long long u; __builtin_memcpy(&u, &v, 8); return u;
}
__device__ __forceinline__ float2 u2f(unsigned long long u) {
    float2 v; __builtin_memcpy(&v, &u, 8); return v;
}
__device__ __forceinline__ float2 ffma2(float2 a, float2 b, float2 c) {
    unsigned long long d;
    asm("fma.rn.f32x2 %0, %1, %2, %3;"
        : "=l"(d) : "l"(f2u(a)), "l"(f2u(b)), "l"(f2u(c)));
    return u2f(d);
}

__global__ __launch_bounds__(THREADS, 6)
void gibbs_sweep_kernel(const float* __restrict__ x,
                        const float* __restrict__ noise,
                        float* __restrict__ out,
                        int B)
{
    // two swizzled float4 row buffers: [row][8 float4], 16 KB each
    __shared__ __align__(16) float4 bufN[ROWS_PER_BLOCK * 8];
    __shared__ __align__(16) float4 bufX[ROWS_PER_BLOCK * 8];

    const int tid = threadIdx.x;
    const int R0  = blockIdx.x * ROWS_PER_BLOCK;

    // ---- front-issue ALL global loads (16 LDG.128), swizzled STS.128 ----
    const float4* gn = (const float4*)noise;
    const float4* gx = (const float4*)x;
    #pragma unroll
    for (int k = 0; k < 8; ++k) {
        int idx = k * THREADS + tid;           // 0..1023, coalesced
        int row = idx >> 3;
        int c   = idx & 7;
        int gr  = R0 + row;
        float4 nv = (gr < B) ? gn[(size_t)gr * 8 + c]
                             : make_float4(0.f, 0.f, 0.f, 0.f);
        bufN[row * 8 + (c ^ ((row >> 2) & 7))] = nv;
    }
    #pragma unroll
    for (int k = 0; k < 8; ++k) {
        int idx = k * THREADS + tid;
        int row = idx >> 3;
        int c   = idx & 7;
        int gr  = R0 + row;
        float4 xv = (gr < B) ? gx[(size_t)gr * 8 + c]
                             : make_float4(0.f, 0.f, 0.f, 0.f);
        bufX[row * 8 + (c ^ ((row >> 2) & 7))] = xv;
    }
    __syncthreads();

    const int sw = (tid >> 2) & 7;

    // ---- r <- base = mu + sigma*noise (LDS.128 chunks + const ffma2) ----
    float2 r[16];
    #pragma unroll
    for (int c = 0; c < 8; ++c) {
        float4 nv = bufN[tid * 8 + (c ^ sw)];
        r[2 * c]     = ffma2(make_float2(nv.x, nv.y), c_SG2[2 * c],     c_MU2[2 * c]);
        r[2 * c + 1] = ffma2(make_float2(nv.z, nv.w), c_SG2[2 * c + 1], c_MU2[2 * c + 1]);
    }

    // ---- Phase 1: r += U x_old, x consumed in float4 chunks ----
    #pragma unroll
    for (int c = 0; c < 8; ++c) {
        float4 xv = bufX[tid * 8 + (c ^ sw)];
        #pragma unroll
        for (int u = 0; u < 4; ++u) {
            const int j = 4 * c + u;
            if (j == 0) continue;              // column 0 upper is empty
            float xj = (u == 0) ? xv.x : (u == 1) ? xv.y : (u == 2) ? xv.z : xv.w;
            float2 xs = make_float2(xj, xj);
            #pragma unroll
            for (int q = 0; q < ((j + 3) >> 2); ++q) {
                float4 col = c_T4[j * 8 + q];  // masked: entries k>=j are 0
                r[2 * q]     = ffma2(xs, make_float2(col.x, col.y), r[2 * q]);
                r[2 * q + 1] = ffma2(xs, make_float2(col.z, col.w), r[2 * q + 1]);
            }
        }
    }

    // ---- Phase 2: forward substitution, column order (no reductions) ----
    #pragma unroll
    for (int j = 0; j < DIM - 1; ++j) {
        float xj = (j & 1) ? r[j >> 1].y : r[j >> 1].x;   // r_j is final = x_j
        float2 xs = make_float2(xj, xj);
        #pragma unroll
        for (int q = j >> 2; q < 8; ++q) {
            float4 col = c_T4[256 + j * 8 + q]; // masked: entries k<=j are 0
            r[2 * q]     = ffma2(xs, make_float2(col.x, col.y), r[2 * q]);
            r[2 * q + 1] = ffma2(xs, make_float2(col.z, col.w), r[2 * q + 1]);
        }
    }

    __syncthreads();   // all phase-1 reads of bufX done before reuse
    // ---- scatter rows to bufX (swizzled), then coalesced STG.128 ----
    #pragma unroll
    for (int c = 0; c < 8; ++c) {
        bufX[tid * 8 + (c ^ sw)] =
            make_float4(r[2 * c].x, r[2 * c].y, r[2 * c + 1].x, r[2 * c + 1].y);
    }
    __syncthreads();
    float4* gout = (float4*)out;
    #pragma unroll
    for (int k = 0; k < 8; ++k) {
        int idx = k * THREADS + tid;
        int row = idx >> 3;
        int c   = idx & 7;
        int gr  = R0 + row;
        if (gr < B) gout[(size_t)gr * 8 + c] = bufX[row * 8 + (c ^ ((row >> 2) & 7))];
    }
}

extern "C" void kernel_launch(void* const* d_in, const int* in_sizes, int n_in,
                              void* d_out, int out_size)
{
    const float* x     = (const float*)d_in[0];
    const float* noise = (const float*)d_in[1];
    const float* P     = (const float*)d_in[2];
    const float* mu    = (const float*)d_in[3];
    float* out = (float*)d_out;

    int B = in_sizes[0] / DIM;

    // 1) build masked column tables + sigma/mu on device
    prep_kernel<<<1, DIM * DIM>>>(P, mu);

    // 2) D2D copies into __constant__ (graph-capturable memcpy nodes)
    void* gT_addr = nullptr; void* gSM_addr = nullptr;
    cudaGetSymbolAddress(&gT_addr, g_T);
    cudaGetSymbolAddress(&gSM_addr, g_SM);
    cudaMemcpyToSymbolAsync(c_T4, gT_addr, sizeof(float) * 2 * DIM * DIM, 0,
                            cudaMemcpyDeviceToDevice, 0);
    cudaMemcpyToSymbolAsync(c_SG2, gSM_addr, sizeof(float) * DIM, 0,
                            cudaMemcpyDeviceToDevice, 0);
    cudaMemcpyToSymbolAsync(c_MU2, (const char*)gSM_addr + sizeof(float) * DIM,
                            sizeof(float) * DIM, 0,
                            cudaMemcpyDeviceToDevice, 0);

    // 3) the sweep
    int grid = (B + ROWS_PER_BLOCK - 1) / ROWS_PER_BLOCK;
    gibbs_sweep_kernel<<<grid, THREADS>>>(x, noise, out, B);
}